// round 14
// baseline (speedup 1.0000x reference)
#include <cuda_runtime.h>
#include <math.h>

// Problem constants
#define B_ 64
#define S_ 1024
#define I_ 300
#define H_ 1024
#define O_ 100
#define T_ 1023        // S-1 timesteps actually computed
#define KT 32          // K tile
#define NTH 256        // threads per block
#define NBLK 130       // 64 L1 + 64 L2 + 2 OUT (all resident: 130 < 148 SMs)

// Persistent state (device globals: no allocation allowed)
__device__ float g_h1[2][B_ * H_];
__device__ float g_h2[2][B_ * H_];
__device__ float g_c1[B_ * H_];
__device__ float g_c2[B_ * H_];
__device__ unsigned g_bar_count;
__device__ volatile unsigned g_bar_gen;

// ---------- packed f32x2 helpers (Blackwell sm_10x: FFMA2) ----------
__device__ __forceinline__ unsigned long long pack2(float v) {
    unsigned long long r;
    unsigned int u = __float_as_uint(v);
    asm("mov.b64 %0, {%1, %1};" : "=l"(r) : "r"(u));
    return r;
}
__device__ __forceinline__ void fma2(unsigned long long& acc,
                                     unsigned long long a,
                                     unsigned long long b) {
    asm("fma.rn.f32x2 %0, %1, %2, %0;" : "+l"(acc) : "l"(a), "l"(b));
}
__device__ __forceinline__ float lo2(unsigned long long v) {
    return __uint_as_float((unsigned int)(v & 0xffffffffull));
}
__device__ __forceinline__ float hi2(unsigned long long v) {
    return __uint_as_float((unsigned int)(v >> 32));
}
__device__ __forceinline__ float sigf(float x) { return 1.0f / (1.0f + expf(-x)); }

// Load 8 consecutive floats with tail guard. LDCG=true bypasses L1
// (required for recurrent state arrays under the persistent kernel —
// no per-launch L1D flush anymore).
template <bool LDCG>
__device__ __forceinline__ void load8(float r[8],
                                      const float* __restrict__ p,
                                      int k0, int K) {
    if (k0 + 8 <= K) {
        float4 a, b;
        if (LDCG) {
            a = __ldcg(reinterpret_cast<const float4*>(p + k0));
            b = __ldcg(reinterpret_cast<const float4*>(p + k0 + 4));
        } else {
            a = *reinterpret_cast<const float4*>(p + k0);
            b = *reinterpret_cast<const float4*>(p + k0 + 4);
        }
        r[0] = a.x; r[1] = a.y; r[2] = a.z; r[3] = a.w;
        r[4] = b.x; r[5] = b.y; r[6] = b.z; r[7] = b.w;
    } else {
        #pragma unroll
        for (int j = 0; j < 8; ++j)
            r[j] = (k0 + j < K) ? (LDCG ? __ldcg(p + k0 + j) : p[k0 + j]) : 0.0f;
    }
}

// ACC[64 rows][64 cols] += U[64 x K] * W[cols]^T over K.
// 256 threads. Thread tile: 4 rows (2 packed f32x2 pairs) x 4 cols.
// Staging double-buffered through registers; stores are bank-conflict-free
// (lb = tid&63 -> 32 consecutive banks per warp).
template <bool UCG>
__device__ __forceinline__ void gemm_accum(
    unsigned long long acc2[2][4],
    float (*uS)[64], float (*wS)[64],
    const float* __restrict__ U, long long ldu,
    const float* __restrict__ W, long long ldw, int wrow,
    int K)
{
    const int tid = threadIdx.x;
    const int lb  = tid & 63;           // staging column (row of U / col of tile)
    const int lk0 = (tid >> 6) * 8;     // this thread's k-offset within the tile
    const int rg  = tid >> 4;           // row group 0..15 (4 rows each)
    const int cg  = tid & 15;           // col group 0..15 (4 cols each)

    const float* up = U + (long long)lb * ldu;
    const float* wp = W + (long long)wrow * ldw;

    float ur[8], wr[8];
    load8<UCG>(ur, up, lk0, K);
    load8<false>(wr, wp, lk0, K);

    const int ntiles = (K + KT - 1) / KT;
    for (int t = 0; t < ntiles; ++t) {
        __syncthreads();   // previous tile's readers are done
        #pragma unroll
        for (int j = 0; j < 8; ++j) {
            uS[lk0 + j][lb] = ur[j];
            wS[lk0 + j][lb] = wr[j];
        }
        __syncthreads();   // tiles published
        if (t + 1 < ntiles) {
            int k0 = (t + 1) * KT + lk0;
            load8<UCG>(ur, up, k0, K);   // LDG latency overlaps compute below
            load8<false>(wr, wp, k0, K);
        }
        #pragma unroll 8
        for (int kk = 0; kk < KT; ++kk) {
            const unsigned long long* u2 =
                reinterpret_cast<const unsigned long long*>(&uS[kk][rg * 4]);
            float4 w = *reinterpret_cast<const float4*>(&wS[kk][cg * 4]);
            unsigned long long w0 = pack2(w.x), w1 = pack2(w.y),
                               w2 = pack2(w.z), w3 = pack2(w.w);
            #pragma unroll
            for (int p = 0; p < 2; ++p) {
                unsigned long long uu = u2[p];   // rows rg*4+2p, rg*4+2p+1
                fma2(acc2[p][0], uu, w0);
                fma2(acc2[p][1], uu, w1);
                fma2(acc2[p][2], uu, w2);
                fma2(acc2[p][3], uu, w3);
            }
        }
    }
}

// LSTM cell update: thread's 4 columns are exactly gates (i,f,g,o) of one unit.
// c-state is owned by this CTA across all intervals (own-L1 coherent).
__device__ __forceinline__ void lstm_epilogue(
    unsigned long long acc2[2][4],
    float* __restrict__ cstate, float* __restrict__ hout, int u0)
{
    const int tid = threadIdx.x;
    const int rg = tid >> 4;
    const int cg = tid & 15;
    const int unit = u0 + cg;
    #pragma unroll
    for (int p = 0; p < 2; ++p) {
        #pragma unroll
        for (int h = 0; h < 2; ++h) {
            int b = rg * 4 + 2 * p + h;
            float iv = h ? hi2(acc2[p][0]) : lo2(acc2[p][0]);
            float fv = h ? hi2(acc2[p][1]) : lo2(acc2[p][1]);
            float gv = h ? hi2(acc2[p][2]) : lo2(acc2[p][2]);
            float ov = h ? hi2(acc2[p][3]) : lo2(acc2[p][3]);
            iv = sigf(iv); fv = sigf(fv); gv = tanhf(gv); ov = sigf(ov);
            long long idx = (long long)b * H_ + unit;
            float cn = fv * cstate[idx] + iv * gv;
            cstate[idx] = cn;
            hout[idx] = ov * tanhf(cn);
        }
    }
}

// Zero recurrent state, barrier, and out[:, 0, :]
__global__ void init_kernel(float* __restrict__ out) {
    int idx = blockIdx.x * blockDim.x + threadIdx.x;
    if (idx == 0) { g_bar_count = 0; g_bar_gen = 0; }
    if (idx < 2 * B_ * H_) {
        ((float*)g_h1)[idx] = 0.0f;
        ((float*)g_h2)[idx] = 0.0f;
    }
    if (idx < B_ * H_) {
        g_c1[idx] = 0.0f;
        g_c2[idx] = 0.0f;
    }
    if (idx < B_ * O_) {
        int b = idx / O_, o = idx % O_;
        out[(long long)b * S_ * O_ + o] = 0.0f;  // t = 0 row is all zeros
    }
}

// Persistent kernel. One pipeline interval k per iteration (k = 0..T_+1):
//   blocks   0..63 : layer-1 -> h1(k)            (active k <= T_-1)
//   blocks  64..127: layer-2 -> h2(k-1)          (active 1 <= k <= T_)
//   blocks 128..129: output  -> out at t = k-1   (active k >= 2)
// Buffers: h1(j) lives in g_h1[j&1]; h2(j) lives in g_h2[j&1].
__global__ void __launch_bounds__(NTH, 1) lstm_persistent(
    const float* __restrict__ x,
    const float* __restrict__ Wih1, const float* __restrict__ Whh1,
    const float* __restrict__ bih1, const float* __restrict__ bhh1,
    const float* __restrict__ Wih2, const float* __restrict__ Whh2,
    const float* __restrict__ bih2, const float* __restrict__ bhh2,
    const float* __restrict__ Wout, const float* __restrict__ bout,
    float* __restrict__ out)
{
    __shared__ float uS[KT][64];
    __shared__ float wS[KT][64];

    const int blk = blockIdx.x;
    const int tid = threadIdx.x;
    const int cg = tid & 15;
    const int lb = tid & 63;   // this thread's weight-load column (0..63)
    const int rg = tid >> 4;

    unsigned long long acc2[2][4];

    for (int k = 0; k <= T_ + 1; ++k) {
        if (blk < 64) {
            // ---- Layer 1: h1(k), c1 from h1(k-1), c1, x[:, k+1, :] ----
            if (k < T_) {
                const int u0 = blk * 16;
                const float* h1prev = g_h1[(k + 1) & 1];   // h1(k-1)
                float* h1out = g_h1[k & 1];                // h1(k)
                #pragma unroll
                for (int i = 0; i < 4; ++i) {
                    int c = cg * 4 + i;
                    int r = (c & 3) * H_ + u0 + (c >> 2);
                    unsigned long long pv = pack2(bih1[r] + bhh1[r]);
                    acc2[0][i] = pv; acc2[1][i] = pv;
                }
                const int wrow = (lb & 3) * H_ + u0 + (lb >> 2);
                gemm_accum<false>(acc2, uS, wS, x + (long long)(k + 1) * I_,
                                  (long long)S_ * I_, Wih1, I_, wrow, I_);
                gemm_accum<true>(acc2, uS, wS, h1prev, H_, Whh1, H_, wrow, H_);
                lstm_epilogue(acc2, g_c1, h1out, u0);
            }
        } else if (blk < 128) {
            // ---- Layer 2: h2(k-1), c2 from h1(k-1), h2(k-2), c2 ----
            if (k >= 1 && k <= T_) {
                const int u0 = (blk - 64) * 16;
                const float* h1prev = g_h1[(k + 1) & 1];   // h1(k-1)
                const float* h2prev = g_h2[k & 1];         // h2(k-2)
                float* h2out = g_h2[(k + 1) & 1];          // h2(k-1)
                #pragma unroll
                for (int i = 0; i < 4; ++i) {
                    int c = cg * 4 + i;
                    int r = (c & 3) * H_ + u0 + (c >> 2);
                    unsigned long long pv = pack2(bih2[r] + bhh2[r]);
                    acc2[0][i] = pv; acc2[1][i] = pv;
                }
                const int wrow = (lb & 3) * H_ + u0 + (lb >> 2);
                gemm_accum<true>(acc2, uS, wS, h1prev, H_, Wih2, H_, wrow, H_);
                gemm_accum<true>(acc2, uS, wS, h2prev, H_, Whh2, H_, wrow, H_);
                lstm_epilogue(acc2, g_c2, h2out, u0);
            }
        } else {
            // ---- Output projection: out(t'=k-2) = h2(k-2) @ Wout^T + bout ----
            if (k >= 2) {
                const int o0 = (blk - 128) * 64;
                const float* h2src = g_h2[k & 1];          // h2(k-2)
                #pragma unroll
                for (int i = 0; i < 4; ++i) {
                    int c = o0 + cg * 4 + i;
                    float bv = (c < O_) ? bout[c] : 0.0f;
                    unsigned long long pv = pack2(bv);
                    acc2[0][i] = pv; acc2[1][i] = pv;
                }
                int wr_ = o0 + lb;
                if (wr_ >= O_) wr_ = O_ - 1;               // clamp; results discarded
                gemm_accum<true>(acc2, uS, wS, h2src, H_, Wout, H_, wr_, H_);

                const int tout = k - 1;                    // out index t'+1
                #pragma unroll
                for (int p = 0; p < 2; ++p) {
                    #pragma unroll
                    for (int h = 0; h < 2; ++h) {
                        int b = rg * 4 + 2 * p + h;
                        #pragma unroll
                        for (int i = 0; i < 4; ++i) {
                            int c = o0 + cg * 4 + i;
                            if (c < O_) {
                                float v = h ? hi2(acc2[p][i]) : lo2(acc2[p][i]);
                                out[((long long)b * S_ + tout) * O_ + c] = v;
                            }
                        }
                    }
                }
            }
        }

        // ---- Grid barrier (all 130 CTAs resident: 130 < 148 SMs) ----
        __threadfence();     // release: this CTA's state writes visible at L2
        __syncthreads();
        if (tid == 0) {
            unsigned gen = g_bar_gen;
            unsigned t = atomicAdd(&g_bar_count, 1u);
            if (t == NBLK - 1) {
                g_bar_count = 0;
                __threadfence();
                g_bar_gen = gen + 1;
            } else {
                while (g_bar_gen == gen) { }
            }
        }
        __syncthreads();
        __threadfence();     // acquire: subsequent reads see other CTAs' writes
    }
}

extern "C" void kernel_launch(void* const* d_in, const int* in_sizes, int n_in,
                              void* d_out, int out_size) {
    const float* x    = (const float*)d_in[0];
    const float* Wih1 = (const float*)d_in[1];
    const float* Whh1 = (const float*)d_in[2];
    const float* bih1 = (const float*)d_in[3];
    const float* bhh1 = (const float*)d_in[4];
    const float* Wih2 = (const float*)d_in[5];
    const float* Whh2 = (const float*)d_in[6];
    const float* bih2 = (const float*)d_in[7];
    const float* bhh2 = (const float*)d_in[8];
    const float* Wout = (const float*)d_in[9];
    const float* bout = (const float*)d_in[10];
    float* out = (float*)d_out;

    init_kernel<<<(2 * B_ * H_ + 255) / 256, 256>>>(out);
    lstm_persistent<<<NBLK, NTH>>>(x, Wih1, Whh1, bih1, bhh1,
                                   Wih2, Whh2, bih2, bhh2, Wout, bout, out);
}